// round 1
// baseline (speedup 1.0000x reference)
#include <cuda_runtime.h>
#include <math_constants.h>

// Problem constants (from reference): B=32, J=11, C=9, M=N=256
#define BB 32
#define JJ 11
#define CC 9
#define MM 256
#define NN 256
#define HW (MM*NN)          // 65536 elements per (b,j) map
#define NBOX (BB*JJ)        // 352

// Staging for per-box losses (device scratch; no allocation allowed)
__device__ float g_box[NBOX];

// Kernel A: per-(b,j) argmax over 256x256 heatmap + per-box loss
__global__ __launch_bounds__(512, 2)
void argmax_loss_kernel(const float* __restrict__ pred,
                        const float* __restrict__ gt,
                        const float* __restrict__ heatmap)
{
    const int bj = blockIdx.x;          // 0..351
    const int b  = bj / JJ;
    const int t  = threadIdx.x;         // 0..511

    const float4* hm = reinterpret_cast<const float4*>(heatmap) + (size_t)bj * (HW / 4);

    // Per-thread scan: 65536/4 = 16384 float4, 512 threads -> 32 vec loads each.
    // Iterate in increasing flat-index order; strict '>' keeps first occurrence.
    float best = -CUDART_INF_F;
    int   bidx = 0;

    #pragma unroll
    for (int k = 0; k < 32; ++k) {
        const int i4 = t + k * 512;
        const float4 v = __ldg(&hm[i4]);
        const int base = i4 * 4;
        if (v.x > best) { best = v.x; bidx = base;     }
        if (v.y > best) { best = v.y; bidx = base + 1; }
        if (v.z > best) { best = v.z; bidx = base + 2; }
        if (v.w > best) { best = v.w; bidx = base + 3; }
    }

    __shared__ float smax[512];
    __shared__ int   sidx[512];
    smax[t] = best;
    sidx[t] = bidx;
    __syncthreads();

    // Tree reduction with first-occurrence (lowest flat index) tie-break.
    #pragma unroll
    for (int s = 256; s > 0; s >>= 1) {
        if (t < s) {
            const float ov = smax[t + s];
            const int   oi = sidx[t + s];
            if (ov > smax[t] || (ov == smax[t] && oi < sidx[t])) {
                smax[t] = ov;
                sidx[t] = oi;
            }
        }
        __syncthreads();
    }

    if (t == 0) {
        const int   idx  = sidx[0];
        const float a_xy = smax[0];
        // reference: x = index // m, y = index % m (m = 256)
        const int x = idx >> 8;
        const int y = idx & 255;

        const float* g = gt + (size_t)bj * 11;   // gt[b, j, 0:11]
        const float gx = g[9];
        const float gy = g[10];

        const bool valid = (gx >= 0.0f) && (gy >= 0.0f) &&
                           (gx < (float)MM) && (gy < (float)NN);

        float loss = 0.0f;
        if (valid) {
            float cls = 0.0f;
            const size_t pbase = ((size_t)b * CC) * HW + (size_t)x * NN + (size_t)y;
            #pragma unroll
            for (int c = 0; c < CC; ++c) {
                const float p = __ldg(&pred[pbase + (size_t)c * HW]);
                const float d = p - g[c];
                cls = fmaf(d, d, cls);
            }
            const float dx = gx - (float)x;
            const float dy = gy - (float)y;
            const float ca = 1.0f - a_xy;
            loss = cls + dx * dx + dy * dy + ca * ca;
        }
        g_box[bj] = loss;
    }
}

// Kernel B: reduce 11 boxes per batch into d_out[b]
__global__ void reduce_kernel(float* __restrict__ out)
{
    const int b = threadIdx.x;
    if (b < BB) {
        float s = 0.0f;
        #pragma unroll
        for (int j = 0; j < JJ; ++j)
            s += g_box[b * JJ + j];
        out[b] = s;
    }
}

extern "C" void kernel_launch(void* const* d_in, const int* in_sizes, int n_in,
                              void* d_out, int out_size)
{
    const float* pred    = (const float*)d_in[0];  // (32, 9, 256, 256)
    const float* gt      = (const float*)d_in[1];  // (32, 11, 11)
    const float* heatmap = (const float*)d_in[2];  // (32, 11, 256, 256)
    float* out = (float*)d_out;                    // (32,)

    argmax_loss_kernel<<<NBOX, 512>>>(pred, gt, heatmap);
    reduce_kernel<<<1, 32>>>(out);
}

// round 2
// speedup vs baseline: 1.2335x; 1.2335x over previous
#include <cuda_runtime.h>
#include <math_constants.h>

// Problem constants: B=32, J=11, C=9, M=N=256
#define BB 32
#define JJ 11
#define CC 9
#define MM 256
#define NN 256
#define HW (MM*NN)            // 65536 elements per (b,j) map
#define NBOX (BB*JJ)          // 352
#define BLOCKS_PER_BOX 2
#define NBLK (NBOX*BLOCKS_PER_BOX)   // 704
#define NTHR 256
#define V4_PER_HALF (HW/4/BLOCKS_PER_BOX)   // 8192 float4 per half-map
#define V4_PER_THREAD (V4_PER_HALF/NTHR)    // 32

// Device scratch (zero-initialized at module load; every field is
// self-resetting within a launch -> safe under graph replay).
__device__ unsigned long long g_key[NBOX];   // packed (value_bits<<32)|(~idx)
__device__ unsigned int       g_cnt[NBOX];   // per-box arrival counter (wraps)
__device__ float              g_box[NBOX];   // per-box loss
__device__ unsigned int       g_done;        // global arrival counter (wraps)

__global__ __launch_bounds__(NTHR, 6)
void label_loss_fused(const float* __restrict__ pred,
                      const float* __restrict__ gt,
                      const float* __restrict__ heatmap,
                      float* __restrict__ out)
{
    const int blk  = blockIdx.x;           // 0..703
    const int box  = blk >> 1;             // 0..351
    const int half = blk & 1;
    const int b    = box / JJ;
    const int t    = threadIdx.x;

    __shared__ float s_val[NTHR / 32];
    __shared__ int   s_idx[NTHR / 32];
    __shared__ bool  s_last;
    if (t == 0) s_last = false;

    // ---- streaming argmax over this half-map ----
    const float4* hm = reinterpret_cast<const float4*>(heatmap)
                     + (size_t)box * (HW / 4) + (size_t)half * V4_PER_HALF;

    float best = -CUDART_INF_F;
    int   bidx = 0;                        // map-local flat index (0..65535)

    #pragma unroll 8
    for (int k = 0; k < V4_PER_THREAD; ++k) {
        const int i4 = t + k * NTHR;       // increasing per thread
        const float4 v = __ldg(&hm[i4]);
        const float m01 = fmaxf(v.x, v.y);
        const float m23 = fmaxf(v.z, v.w);
        const float m4  = fmaxf(m01, m23);
        if (m4 > best) {
            best = m4;
            const int base = (half * V4_PER_HALF + i4) * 4;
            int lane;
            if      (v.x == m4) lane = 0;
            else if (v.y == m4) lane = 1;
            else if (v.z == m4) lane = 2;
            else                lane = 3;
            bidx = base + lane;
        }
    }

    // ---- warp reduce (value desc, idx asc tie-break) ----
    #pragma unroll
    for (int off = 16; off > 0; off >>= 1) {
        const float ov = __shfl_down_sync(0xFFFFFFFFu, best, off);
        const int   oi = __shfl_down_sync(0xFFFFFFFFu, bidx, off);
        if (ov > best || (ov == best && oi < bidx)) { best = ov; bidx = oi; }
    }
    if ((t & 31) == 0) {
        s_val[t >> 5] = best;
        s_idx[t >> 5] = bidx;
    }
    __syncthreads();

    if (t == 0) {
        #pragma unroll
        for (int w = 1; w < NTHR / 32; ++w) {
            const float ov = s_val[w];
            const int   oi = s_idx[w];
            if (ov > best || (ov == best && oi < bidx)) { best = ov; bidx = oi; }
        }

        // Pack: higher value wins; on tie smaller idx wins (~idx is larger).
        const unsigned long long key =
            ((unsigned long long)__float_as_uint(best) << 32) |
            (unsigned int)(~(unsigned int)bidx);
        atomicMax(&g_key[box], key);
        __threadfence();

        // Per-box arrival; wraps to 0 at BLOCKS_PER_BOX-1 -> self-reset.
        const unsigned prev = atomicInc(&g_cnt[box], BLOCKS_PER_BOX - 1);
        if (prev == BLOCKS_PER_BOX - 1) {
            // Last block for this box: read-and-reset the key.
            const unsigned long long cur = atomicExch(&g_key[box], 0ULL);
            const float a_xy = __uint_as_float((unsigned int)(cur >> 32));
            const int   idx  = (int)(~(unsigned int)cur);
            const int x = idx >> 8;       // index // 256
            const int y = idx & 255;      // index % 256

            const float* g = gt + (size_t)box * 11;
            const float gx = g[9];
            const float gy = g[10];
            const bool valid = (gx >= 0.0f) && (gy >= 0.0f) &&
                               (gx < (float)MM) && (gy < (float)NN);

            float loss = 0.0f;
            if (valid) {
                float cls = 0.0f;
                const size_t pbase = ((size_t)b * CC) * HW
                                   + (size_t)x * NN + (size_t)y;
                #pragma unroll
                for (int c = 0; c < CC; ++c) {
                    const float p = __ldg(&pred[pbase + (size_t)c * HW]);
                    const float d = p - g[c];
                    cls = fmaf(d, d, cls);
                }
                const float dx = gx - (float)x;
                const float dy = gy - (float)y;
                const float ca = 1.0f - a_xy;
                loss = cls + dx * dx + dy * dy + ca * ca;
            }
            g_box[box] = loss;
            __threadfence();

            // Global arrival; wraps to 0 at NBOX-1 -> self-reset.
            const unsigned p2 = atomicInc(&g_done, NBOX - 1);
            if (p2 == NBOX - 1) s_last = true;
        }
    }
    __syncthreads();

    // ---- the very last box-finisher's block writes the output ----
    if (s_last && t < BB) {
        __threadfence();
        volatile float* vb = g_box;
        float s = 0.0f;
        #pragma unroll
        for (int j = 0; j < JJ; ++j)
            s += vb[t * JJ + j];
        out[t] = s;
    }
}

extern "C" void kernel_launch(void* const* d_in, const int* in_sizes, int n_in,
                              void* d_out, int out_size)
{
    const float* pred    = (const float*)d_in[0];  // (32, 9, 256, 256)
    const float* gt      = (const float*)d_in[1];  // (32, 11, 11)
    const float* heatmap = (const float*)d_in[2];  // (32, 11, 256, 256)
    float* out = (float*)d_out;                    // (32,)

    label_loss_fused<<<NBLK, NTHR>>>(pred, gt, heatmap, out);
}